// round 8
// baseline (speedup 1.0000x reference)
#include <cuda_runtime.h>
#include <cuda_bf16.h>
#include <cstdint>

// ---------------- problem constants ----------------
#define NS      512
#define KSEG    16
#define SEGD    8192
#define FSTRIDE (KSEG * SEGD)
#define OP_SCALE 1.1952286093343936f   // 1/sqrt(0.7) folded per operand
#define NCLASS  10

// ---------------- fused kernel config ----------------
#define NCTAS   304                    // 2 CTAs per SM
#define NTHREADS 192                   // 4 MMA warps + 2 convert warps
#define MT      64                     // class tile
#define CK      64                     // bf16 per chunk (128B rows, SW128)
#define KQ      2048                   // K per unit (quarter)
#define CHPU    (KQ / CK)              // 32 chunks per unit
#define STAGES  4
#define OP_BYTES    (MT * 128)         // 8192
#define STAGE_BYTES (2 * OP_BYTES)     // 16384
#define SMEM_DYN (1024 + STAGES * STAGE_BYTES)  // 66560 -> 2 CTAs/SM

#define NROWPAD 640                    // grouped rows padded (zeros beyond 512)
#define MAXP    32                     // max class tile-pairs total
#define NPLANES (KSEG * 4)             // (seg, kq) release planes

// ---------------- device scratch ----------------
__device__ __align__(16) __nv_bfloat16 g_fb16[(size_t)KSEG * NROWPAD * SEGD];
__device__ float g_gram[(size_t)NPLANES * MAXP * MT * MT];   // 33.5 MB
__device__ float g_partials[1024];
__device__ int   g_red_count;
__device__ int   g_unit;
__device__ int   g_plcnt[NPLANES];
__device__ int   g_plflag[NPLANES];
// schedule (built by prep each launch; deterministic)
__device__ int   g_pos[NS];            // original index -> grouped row
__device__ int   g_cstart[NCLASS], g_cnum[NCLASS], g_cT[NCLASS], g_cpbase[NCLASS];
__device__ int   g_pairM[MAXP], g_pairN[MAXP];
__device__ int   g_P;

// ---------------- helpers ----------------
__device__ __forceinline__ uint32_t smem_u32(const void* p) {
    uint32_t a;
    asm("{ .reg .u64 t; cvta.to.shared.u64 t, %1; cvt.u32.u64 %0, t; }" : "=r"(a) : "l"(p));
    return a;
}
#define CP16(dst, src) \
    asm volatile("cp.async.cg.shared.global [%0], [%1], 16;" :: "r"(dst), "l"(src))
#define CP_COMMIT() asm volatile("cp.async.commit_group;" ::: "memory")
template <int N> __device__ __forceinline__ void cp_wait() {
    asm volatile("cp.async.wait_group %0;" :: "n"(N) : "memory");
}
#define SW128(o) ((o) ^ (((o) >> 3) & 0x70))
#define BAR_MMA()  asm volatile("bar.sync 1, 128;" ::: "memory")
#define BAR_CONV() asm volatile("bar.sync 2, 64;"  ::: "memory")

__device__ __forceinline__ void ldsm_x4(uint32_t& r0, uint32_t& r1, uint32_t& r2, uint32_t& r3,
                                        uint32_t addr) {
    asm volatile("ldmatrix.sync.aligned.m8n8.x4.shared.b16 {%0,%1,%2,%3}, [%4];"
                 : "=r"(r0), "=r"(r1), "=r"(r2), "=r"(r3) : "r"(addr));
}
__device__ __forceinline__ void mma16816(float* c, const uint32_t* a, uint32_t b0, uint32_t b1) {
    asm volatile(
        "mma.sync.aligned.m16n8k16.row.col.f32.bf16.bf16.f32 "
        "{%0,%1,%2,%3}, {%4,%5,%6,%7}, {%8,%9}, {%0,%1,%2,%3};"
        : "+f"(c[0]), "+f"(c[1]), "+f"(c[2]), "+f"(c[3])
        : "r"(a[0]), "r"(a[1]), "r"(a[2]), "r"(a[3]), "r"(b0), "r"(b1));
}

// ---------------------------------------------------------------------------
// Prep (1 block, 512 threads): label dtype detect, stable count-sort by label,
// per-class tile-pair schedule. All deterministic (sequential in thread 0).
// ---------------------------------------------------------------------------
__global__ void prep_kernel(const int* __restrict__ lab) {
    __shared__ int sh_lab[NS];
    __shared__ int cnt[NCLASS];
    const int t = threadIdx.x;
    // int32 vs int64: labels 0..9 -> odd 32-bit words all zero iff int64
    int viol = (lab[2 * t + 1] != 0) ? 1 : 0;
    int is32 = __syncthreads_or(viol);
    int v = is32 ? lab[t] : lab[2 * t];
    sh_lab[t] = v;
    if (t < NCLASS) cnt[t] = 0;
    __syncthreads();
    atomicAdd(&cnt[v], 1);
    __syncthreads();
    if (t == 0) {
        int start = 0, P = 0;
        int run[NCLASS];
        for (int c = 0; c < NCLASS; c++) {
            int n = cnt[c];
            g_cstart[c] = start; g_cnum[c] = n;
            int T = (n + MT - 1) / MT;
            g_cT[c] = T; g_cpbase[c] = P;
            for (int ti = 0; ti < T; ti++)
                for (int tj = ti; tj < T; tj++) {
                    if (P < MAXP) { g_pairM[P] = start + MT * ti; g_pairN[P] = start + MT * tj; }
                    P++;
                }
            run[c] = 0;
            start += n;
        }
        g_P = (P > MAXP) ? MAXP : P;
        for (int n = 0; n < NS; n++) {
            int c = sh_lab[n];
            g_pos[n] = g_cstart[c] + run[c]++;
        }
    }
}

// ---------------------------------------------------------------------------
// Fused convert + block-diagonal GEMM. 304 CTAs (2/SM), 192 threads.
//   warps 0-3 : bf16 HMMA GEMM (128 threads, bar 1), 2x2 warp grid of 32x32
//               tiles over a 64x64 class tile, 4-stage cp.async.
//   warps 4-5 : f32 -> bf16 producer into label-grouped layout; releases the
//               64 (seg, kq) planes in queue-consumption order.
// Unit u -> (plane = u / P, pair = u % P). Disjoint outputs => deterministic.
// ---------------------------------------------------------------------------
__global__ void __launch_bounds__(NTHREADS, 2)
fused_kernel(const float* __restrict__ F) {
    extern __shared__ __align__(1024) char smem_raw[];
    __shared__ int s_unit;
    const int tid = threadIdx.x;
    const int cta = blockIdx.x;

    if (tid >= 128) {
        // ---------------- producer: convert warps ----------------
        const int tc = tid - 128;                       // 0..63
        const uint32_t GPL = (NS * KQ) / 8;             // 131072 groups / plane
        const uint32_t lo = (uint32_t)(((uint64_t)cta * GPL) / NCTAS);
        const uint32_t hi = (uint32_t)(((uint64_t)(cta + 1) * GPL) / NCTAS);
        for (int pl = 0; pl < NPLANES; pl++) {
            const int s = pl >> 2, kq = pl & 3;
            const size_t soff = (size_t)s * SEGD + (size_t)kq * KQ;
#pragma unroll 4
            for (uint32_t i = lo + tc; i < hi; i += 64) {
                uint32_t e = i * 8;
                uint32_t n = e >> 11, dl = e & 2047;    // KQ = 2048
                const float4* src = (const float4*)(F + (size_t)n * FSTRIDE + soff + dl);
                float4 a = src[0], b = src[1];
                a.x *= OP_SCALE; a.y *= OP_SCALE; a.z *= OP_SCALE; a.w *= OP_SCALE;
                b.x *= OP_SCALE; b.y *= OP_SCALE; b.z *= OP_SCALE; b.w *= OP_SCALE;
                __nv_bfloat162 h0 = __floats2bfloat162_rn(a.x, a.y);
                __nv_bfloat162 h1 = __floats2bfloat162_rn(a.z, a.w);
                __nv_bfloat162 h2 = __floats2bfloat162_rn(b.x, b.y);
                __nv_bfloat162 h3 = __floats2bfloat162_rn(b.z, b.w);
                uint4 w;
                w.x = *(uint32_t*)&h0; w.y = *(uint32_t*)&h1;
                w.z = *(uint32_t*)&h2; w.w = *(uint32_t*)&h3;
                int row = g_pos[n];
                *(uint4*)(g_fb16 + ((size_t)s * NROWPAD + row) * SEGD + kq * KQ + dl) = w;
            }
            BAR_CONV();
            if (tc == 0) {
                __threadfence();
                if (atomicAdd(&g_plcnt[pl], 1) == NCTAS - 1) {
                    __threadfence();
                    atomicExch(&g_plflag[pl], 1);       // release plane
                }
            }
        }
        return;
    }

    // ---------------- consumer: 4 MMA warps ----------------
    uint32_t sbase = (smem_u32(smem_raw) + 1023) & ~1023u;
    const int lane = tid & 31;
    const int wid  = tid >> 5;
    const int wm   = wid & 1;            // 2 warps along M
    const int wn   = wid >> 1;           // 2 warps along N
    const int lrow = lane & 15;
    const int khf  = (lane >> 4) & 1;
    const int gid  = lane >> 2, tig = lane & 3;

    const int P = g_P;
    const int NUNITS = NPLANES * P;
    int lastFl = -1;

    for (;;) {
        if (tid == 0) s_unit = atomicAdd(&g_unit, 1);
        BAR_MMA();
        const int u = s_unit;
        if (u >= NUNITS) break;

        const int pl   = u / P;          // ascending with u: matches release order
        const int pidx = u - pl * P;
        const int seg  = pl >> 2, kq = pl & 3;
        const int Moff = g_pairM[pidx];
        const int Noff = g_pairN[pidx];

        if (pl != lastFl) {              // acquire producer plane
            if (tid == 0) {
                while (atomicAdd(&g_plflag[pl], 0) == 0) __nanosleep(200);
            }
            BAR_MMA();
            lastFl = pl;
        }

        const __nv_bfloat16* gA = g_fb16 + ((size_t)seg * NROWPAD + Moff) * SEGD + kq * KQ;
        const __nv_bfloat16* gB = g_fb16 + ((size_t)seg * NROWPAD + Noff) * SEGD + kq * KQ;

        float acc[2][4][4];
#pragma unroll
        for (int i = 0; i < 2; i++)
#pragma unroll
            for (int j = 0; j < 4; j++)
#pragma unroll
                for (int q = 0; q < 4; q++) acc[i][j][q] = 0.0f;

        auto load_chunk = [&](int c) {
            uint32_t st = sbase + (c & (STAGES - 1)) * STAGE_BYTES;
            int kb = c * CK;
#pragma unroll
            for (int i = 0; i < 8; i++) {            // 1024 x 16B over 128 thr
                int q = i * 128 + tid;
                int row = q >> 3, g = q & 7;
                if (row < MT) {
                    CP16(st + SW128(row * 128 + g * 16),
                         gA + (size_t)row * SEGD + kb + g * 8);
                } else {
                    int r2 = row - MT;
                    CP16(st + OP_BYTES + SW128(r2 * 128 + g * 16),
                         gB + (size_t)r2 * SEGD + kb + g * 8);
                }
            }
            CP_COMMIT();
        };

        auto compute = [&](int cs) {
            uint32_t sa = sbase + cs * STAGE_BYTES;
            uint32_t sb = sa + OP_BYTES;
#pragma unroll
            for (int ks = 0; ks < 4; ks++) {
                const int kb = ks * 32 + khf * 16;
                uint32_t a[2][4], bf[2][4];
#pragma unroll
                for (int im = 0; im < 2; im++) {
                    int row = wm * 32 + im * 16 + lrow;
                    ldsm_x4(a[im][0], a[im][1], a[im][2], a[im][3],
                            sa + SW128(row * 128 + kb));
                }
#pragma unroll
                for (int j2 = 0; j2 < 2; j2++) {
                    int row = wn * 32 + j2 * 16 + lrow;
                    ldsm_x4(bf[j2][0], bf[j2][1], bf[j2][2], bf[j2][3],
                            sb + SW128(row * 128 + kb));
                }
#pragma unroll
                for (int im = 0; im < 2; im++)
#pragma unroll
                    for (int jn = 0; jn < 4; jn++)
                        mma16816(acc[im][jn], a[im],
                                 bf[jn >> 1][jn & 1], bf[jn >> 1][2 + (jn & 1)]);
            }
        };

        load_chunk(0); load_chunk(1); load_chunk(2);
        for (int c = 0; c < CHPU; c++) {
            cp_wait<2>();
            BAR_MMA();
            compute(c & (STAGES - 1));
            if (c + 3 < CHPU) load_chunk(c + 3);
            else CP_COMMIT();
        }

        float* Cb = g_gram + ((size_t)pl * MAXP + pidx) * (MT * MT);
#pragma unroll
        for (int im = 0; im < 2; im++) {
#pragma unroll
            for (int jn = 0; jn < 4; jn++) {
                int r0 = wm * 32 + im * 16 + gid;
                int c0 = wn * 32 + jn * 8 + tig * 2;
                *(float2*)&Cb[r0 * MT + c0] =
                    make_float2(acc[im][jn][0], acc[im][jn][1]);
                *(float2*)&Cb[(r0 + 8) * MT + c0] =
                    make_float2(acc[im][jn][2], acc[im][jn][3]);
            }
        }
    }
}

// ---------------------------------------------------------------------------
// Loss over within-class pairs only (i < j, weight 2). Sums 4 K-partials,
// top-4-of-16 exp ratio; deterministic tree reduce; last block writes mean
// and resets queue/flags/counters for graph replay.
// Grid: 10 classes x 64 blocks (i, j in [0,128) per class).
// ---------------------------------------------------------------------------
__global__ __launch_bounds__(256) void reduce_kernel(float* __restrict__ out) {
    const int t     = threadIdx.x;
    const int c     = blockIdx.x >> 6;
    const int local = ((blockIdx.x & 63) << 8) + t;
    const int i = local >> 7;
    const int j = local & 127;

    float loss = 0.0f;
    const int nc = g_cnum[c];
    if (i < j && j < nc) {
        const int T  = g_cT[c];
        const int ti = i >> 6, tj = j >> 6;
        const int pidx = g_cpbase[c] + ti * T - (ti * (ti - 1)) / 2 + (tj - ti);
        const int cell = (i & 63) * MT + (j & 63);

        float v[KSEG];
        float m = -1e30f;
#pragma unroll
        for (int k = 0; k < KSEG; k++) {
            float s = 0.0f;
#pragma unroll
            for (int kq = 0; kq < 4; kq++)
                s += g_gram[((size_t)(k * 4 + kq) * MAXP + pidx) * (MT * MT) + cell];
            v[k] = s;
            m = fmaxf(m, s);
        }
        float tot = 0.0f, t0 = 0.0f, t1 = 0.0f, t2 = 0.0f, t3 = 0.0f;
#pragma unroll
        for (int k = 0; k < KSEG; k++) {
            const float e = __expf(v[k] - m);
            tot += e;
            if (e > t0)      { t3 = t2; t2 = t1; t1 = t0; t0 = e; }
            else if (e > t1) { t3 = t2; t2 = t1; t1 = e; }
            else if (e > t2) { t3 = t2; t2 = e; }
            else if (e > t3) { t3 = e; }
        }
        loss = -2.0f * __logf((t0 + t1 + t2 + t3) / tot);   // both orders
    }

    __shared__ float red[256];
    red[t] = loss;
    __syncthreads();
#pragma unroll
    for (int s = 128; s > 0; s >>= 1) {
        if (t < s) red[t] += red[t + s];
        __syncthreads();
    }

    __shared__ int isLast;
    if (t == 0) {
        g_partials[blockIdx.x] = red[0];
        __threadfence();
        int cn = atomicAdd(&g_red_count, 1);
        isLast = (cn == gridDim.x - 1);
    }
    __syncthreads();

    if (isLast) {
        float s = __ldcg(&g_partials[t]) + __ldcg(&g_partials[t + 256]);
        if (t + 512 < 640) s += __ldcg(&g_partials[t + 512]);
        red[t] = s;
        __syncthreads();
#pragma unroll
        for (int sh = 128; sh > 0; sh >>= 1) {
            if (t < sh) red[t] += red[t + sh];
            __syncthreads();
        }
        if (t == 0) {
            out[0] = red[0] / (float)(NS * NS);
            g_red_count = 0;                        // reset for graph replay
            g_unit = 0;
#pragma unroll
            for (int k = 0; k < NPLANES; k++) { g_plcnt[k] = 0; g_plflag[k] = 0; }
        }
    }
}

// ---------------------------------------------------------------------------
extern "C" void kernel_launch(void* const* d_in, const int* in_sizes, int n_in,
                              void* d_out, int out_size) {
    const float* features = (const float*)d_in[0];
    const int*   labels   = (const int*)d_in[1];
    (void)in_sizes; (void)n_in; (void)out_size;

    cudaFuncSetAttribute(fused_kernel, cudaFuncAttributeMaxDynamicSharedMemorySize, SMEM_DYN);

    prep_kernel<<<1, NS>>>(labels);
    fused_kernel<<<NCTAS, NTHREADS, SMEM_DYN>>>(features);
    reduce_kernel<<<NCLASS * 64, 256>>>((float*)d_out);
}

// round 9
// speedup vs baseline: 2.3164x; 2.3164x over previous
#include <cuda_runtime.h>
#include <cuda_bf16.h>
#include <cstdint>

// ---------------- problem constants ----------------
#define NS      512
#define KSEG    16
#define SEGD    8192
#define FSTRIDE (KSEG * SEGD)
#define OP_SCALE 1.1952286093343936f   // 1/sqrt(0.7) folded per operand
#define NCLASS  10

// ---------------- GEMM config ----------------
#define MT      64                     // class tile
#define CK      64                     // bf16 cols per chunk (128B rows, SW128)
#define KSPLIT  4
#define KQ      (SEGD / KSPLIT)        // 2048
#define CHPU    (KQ / CK)              // 32 chunks per unit
#define OP_BYTES (MT * 128)            // 8192 per operand buffer

#define NROWPAD 640                    // grouped rows padded
#define MAXP    32                     // max class tile-pairs
#define NPL     (KSEG * KSPLIT)        // 64 gram planes

// ---------------- device scratch ----------------
__device__ float g_gram[(size_t)NPL * MAXP * MT * MT];  // 33.5 MB partials
__device__ float g_partials[1024];
__device__ int   g_red_count;
// schedule (rebuilt by prep every launch; deterministic)
__device__ int   g_rowsrc[NROWPAD];    // grouped row -> original sample
__device__ int   g_cnum[NCLASS], g_cT[NCLASS], g_cpbase[NCLASS];
__device__ int   g_pairM[MAXP], g_pairN[MAXP];
__device__ int   g_P;

// ---------------- helpers ----------------
__device__ __forceinline__ uint32_t smem_u32(const void* p) {
    uint32_t a;
    asm("{ .reg .u64 t; cvta.to.shared.u64 t, %1; cvt.u32.u64 %0, t; }" : "=r"(a) : "l"(p));
    return a;
}
#define SW128(o) ((o) ^ (((o) >> 3) & 0x70))

__device__ __forceinline__ void ldsm_x4(uint32_t& r0, uint32_t& r1, uint32_t& r2, uint32_t& r3,
                                        uint32_t addr) {
    asm volatile("ldmatrix.sync.aligned.m8n8.x4.shared.b16 {%0,%1,%2,%3}, [%4];"
                 : "=r"(r0), "=r"(r1), "=r"(r2), "=r"(r3) : "r"(addr));
}
__device__ __forceinline__ void mma16816(float* c, const uint32_t* a, uint32_t b0, uint32_t b1) {
    asm volatile(
        "mma.sync.aligned.m16n8k16.row.col.f32.bf16.bf16.f32 "
        "{%0,%1,%2,%3}, {%4,%5,%6,%7}, {%8,%9}, {%0,%1,%2,%3};"
        : "+f"(c[0]), "+f"(c[1]), "+f"(c[2]), "+f"(c[3])
        : "r"(a[0]), "r"(a[1]), "r"(a[2]), "r"(a[3]), "r"(b0), "r"(b1));
}
// 8 scaled f32 -> uint4 of bf16x2
__device__ __forceinline__ uint4 cvt8(const float4& a, const float4& b) {
    __nv_bfloat162 h0 = __floats2bfloat162_rn(a.x * OP_SCALE, a.y * OP_SCALE);
    __nv_bfloat162 h1 = __floats2bfloat162_rn(a.z * OP_SCALE, a.w * OP_SCALE);
    __nv_bfloat162 h2 = __floats2bfloat162_rn(b.x * OP_SCALE, b.y * OP_SCALE);
    __nv_bfloat162 h3 = __floats2bfloat162_rn(b.z * OP_SCALE, b.w * OP_SCALE);
    uint4 v;
    v.x = *(uint32_t*)&h0; v.y = *(uint32_t*)&h1;
    v.z = *(uint32_t*)&h2; v.w = *(uint32_t*)&h3;
    return v;
}

// ---------------------------------------------------------------------------
// Prep (1 block, 512 threads, ~4us): label dtype detect, deterministic
// rank-by-scan grouping (stable sort by label), tile-pair schedule.
// ---------------------------------------------------------------------------
__global__ void prep_kernel(const int* __restrict__ lab) {
    __shared__ int sl[NS];
    __shared__ int cnt[NCLASS];
    __shared__ int cstart_s[NCLASS];
    const int t = threadIdx.x;
    // int32 vs int64: labels 0..9 -> odd 32-bit words all zero iff int64
    int viol = (lab[2 * t + 1] != 0) ? 1 : 0;
    int is32 = __syncthreads_or(viol);
    const int v = is32 ? lab[t] : lab[2 * t];
    sl[t] = v;
    if (t < NCLASS) cnt[t] = 0;
    __syncthreads();
    // stable rank: count earlier samples with same label (parallel, determ.)
    int rank = 0;
    for (int i = 0; i < NS; i++)
        if (i < t && sl[i] == v) rank++;
    atomicAdd(&cnt[v], 1);
    // init rowsrc padding
    g_rowsrc[t] = 0;
    if (t < NROWPAD - NS) g_rowsrc[NS + t] = 0;
    __syncthreads();
    if (t == 0) {
        int start = 0, P = 0;
        for (int c = 0; c < NCLASS; c++) {
            const int n = cnt[c];
            cstart_s[c] = start;
            g_cnum[c] = n;
            const int T = (n + MT - 1) / MT;
            g_cT[c] = T;
            g_cpbase[c] = P;
            for (int ti = 0; ti < T; ti++)
                for (int tj = ti; tj < T; tj++) {
                    if (P < MAXP) {
                        g_pairM[P] = start + MT * ti;
                        g_pairN[P] = start + MT * tj;
                    }
                    P++;
                }
            start += n;
        }
        g_P = (P > MAXP) ? MAXP : P;
    }
    __syncthreads();
    g_rowsrc[cstart_s[v] + rank] = t;   // grouped row -> original index
}

// ---------------------------------------------------------------------------
// Block-diagonal Gram GEMM reading f32 directly (no staging buffer, no sync).
// Grid (MAXP, KSEG, KSPLIT); CTAs with pidx >= g_P exit. 128 threads:
// 2x2 warp grid of 32x32 tiles over a 64x64 class tile. Per chunk: LDG 64x64
// f32 (gathered rows), cvt->bf16 (scale folded), STS SW128; register prefetch
// of next chunk; MMA from single smem buffer (A==B for diagonal pairs).
// ---------------------------------------------------------------------------
__global__ void __launch_bounds__(128)
gemm_kernel(const float* __restrict__ F) {
    const int pidx = blockIdx.x;
    if (pidx >= g_P) return;
    const int seg = blockIdx.y;
    const int kq  = blockIdx.z;

    __shared__ __align__(1024) char smem[2 * OP_BYTES];
    const uint32_t sa = smem_u32(smem);
    const uint32_t sb_off = OP_BYTES;

    const int tid  = threadIdx.x;
    const int lane = tid & 31;
    const int wid  = tid >> 5;
    const int wm   = wid & 1;
    const int wn   = wid >> 1;
    const int lrow = lane & 15;
    const int khf  = (lane >> 4) & 1;
    const int gid  = lane >> 2, tig = lane & 3;

    const int Moff = g_pairM[pidx];
    const int Noff = g_pairN[pidx];
    const bool diag = (Moff == Noff);

    // loader mapping: 2 threads per row, 32 f32 columns each
    const int lrw = tid >> 1;           // 0..63
    const int ch  = tid & 1;            // column half
    const size_t base = (size_t)seg * SEGD + (size_t)kq * KQ + ch * 32;
    const float* __restrict__ srcA = F + (size_t)g_rowsrc[Moff + lrw] * FSTRIDE + base;
    const float* __restrict__ srcB = diag ? srcA
                                   : F + (size_t)g_rowsrc[Noff + lrw] * FSTRIDE + base;
    const uint32_t stsbase = (uint32_t)(lrw * 128 + ch * 64);

    float acc[2][4][4];
#pragma unroll
    for (int i = 0; i < 2; i++)
#pragma unroll
        for (int j = 0; j < 4; j++)
#pragma unroll
            for (int q = 0; q < 4; q++) acc[i][j][q] = 0.0f;

    // register prefetch buffer for A (B path rare: loaded inline)
    float4 v[8];
#pragma unroll
    for (int q = 0; q < 8; q++) v[q] = ((const float4*)(srcA))[q];

    for (int c = 0; c < CHPU; c++) {
        // store prefetched A chunk (cvt+STS, swizzled)
#pragma unroll
        for (int q = 0; q < 4; q++)
            *(uint4*)(smem + SW128(stsbase + q * 16)) = cvt8(v[2 * q], v[2 * q + 1]);
        if (!diag) {
            const float4* pB = (const float4*)(srcB + (size_t)c * CK);
#pragma unroll
            for (int q = 0; q < 4; q++)
                *(uint4*)(smem + sb_off + SW128(stsbase + q * 16)) =
                    cvt8(pB[2 * q], pB[2 * q + 1]);
        }
        __syncthreads();
        // prefetch next A chunk (completes under the MMAs)
        if (c + 1 < CHPU) {
            const float4* pA = (const float4*)(srcA + (size_t)(c + 1) * CK);
#pragma unroll
            for (int q = 0; q < 8; q++) v[q] = pA[q];
        }
        // MMA on chunk c
        const uint32_t sA = sa;
        const uint32_t sB = diag ? sa : (sa + sb_off);
#pragma unroll
        for (int ks = 0; ks < 4; ks++) {
            const int kb = ks * 32 + khf * 16;
            uint32_t a[2][4], bf[2][4];
#pragma unroll
            for (int im = 0; im < 2; im++) {
                int row = wm * 32 + im * 16 + lrow;
                ldsm_x4(a[im][0], a[im][1], a[im][2], a[im][3],
                        sA + SW128(row * 128 + kb));
            }
#pragma unroll
            for (int j2 = 0; j2 < 2; j2++) {
                int row = wn * 32 + j2 * 16 + lrow;
                ldsm_x4(bf[j2][0], bf[j2][1], bf[j2][2], bf[j2][3],
                        sB + SW128(row * 128 + kb));
            }
#pragma unroll
            for (int im = 0; im < 2; im++)
#pragma unroll
                for (int jn = 0; jn < 4; jn++)
                    mma16816(acc[im][jn], a[im],
                             bf[jn >> 1][jn & 1], bf[jn >> 1][2 + (jn & 1)]);
        }
        __syncthreads();
    }

    float* Cb = g_gram + ((size_t)(seg * KSPLIT + kq) * MAXP + pidx) * (MT * MT);
#pragma unroll
    for (int im = 0; im < 2; im++) {
#pragma unroll
        for (int jn = 0; jn < 4; jn++) {
            int r0 = wm * 32 + im * 16 + gid;
            int c0 = wn * 32 + jn * 8 + tig * 2;
            *(float2*)&Cb[r0 * MT + c0] =
                make_float2(acc[im][jn][0], acc[im][jn][1]);
            *(float2*)&Cb[(r0 + 8) * MT + c0] =
                make_float2(acc[im][jn][2], acc[im][jn][3]);
        }
    }
}

// ---------------------------------------------------------------------------
// Loss over within-class pairs only (i < j, weight 2). Sums 4 K-partials,
// top-4-of-16 exp ratio; deterministic tree reduce; last block writes mean.
// Grid: NCLASS x 64 blocks (i, j in [0,128) per class).
// ---------------------------------------------------------------------------
__global__ __launch_bounds__(256) void reduce_kernel(float* __restrict__ out) {
    const int t     = threadIdx.x;
    const int c     = blockIdx.x >> 6;
    const int local = ((blockIdx.x & 63) << 8) + t;
    const int i = local >> 7;
    const int j = local & 127;

    float loss = 0.0f;
    const int nc = g_cnum[c];
    if (i < j && j < nc) {
        const int T  = g_cT[c];
        const int ti = i >> 6, tj = j >> 6;
        const int pidx = g_cpbase[c] + ti * T - (ti * (ti - 1)) / 2 + (tj - ti);
        const int cell = (i & 63) * MT + (j & 63);

        float v[KSEG];
        float m = -1e30f;
#pragma unroll
        for (int k = 0; k < KSEG; k++) {
            float s = 0.0f;
#pragma unroll
            for (int kq = 0; kq < KSPLIT; kq++)
                s += g_gram[((size_t)(k * KSPLIT + kq) * MAXP + pidx) * (MT * MT) + cell];
            v[k] = s;
            m = fmaxf(m, s);
        }
        float tot = 0.0f, t0 = 0.0f, t1 = 0.0f, t2 = 0.0f, t3 = 0.0f;
#pragma unroll
        for (int k = 0; k < KSEG; k++) {
            const float e = __expf(v[k] - m);
            tot += e;
            if (e > t0)      { t3 = t2; t2 = t1; t1 = t0; t0 = e; }
            else if (e > t1) { t3 = t2; t2 = t1; t1 = e; }
            else if (e > t2) { t3 = t2; t2 = e; }
            else if (e > t3) { t3 = e; }
        }
        loss = -2.0f * __logf((t0 + t1 + t2 + t3) / tot);   // both (a,b),(b,a)
    }

    __shared__ float red[256];
    red[t] = loss;
    __syncthreads();
#pragma unroll
    for (int s = 128; s > 0; s >>= 1) {
        if (t < s) red[t] += red[t + s];
        __syncthreads();
    }

    __shared__ int isLast;
    if (t == 0) {
        g_partials[blockIdx.x] = red[0];
        __threadfence();
        int cn = atomicAdd(&g_red_count, 1);
        isLast = (cn == gridDim.x - 1);
    }
    __syncthreads();

    if (isLast) {
        float s = __ldcg(&g_partials[t]) + __ldcg(&g_partials[t + 256]);
        if (t + 512 < 640) s += __ldcg(&g_partials[t + 512]);
        red[t] = s;
        __syncthreads();
#pragma unroll
        for (int sh = 128; sh > 0; sh >>= 1) {
            if (t < sh) red[t] += red[t + sh];
            __syncthreads();
        }
        if (t == 0) {
            out[0] = red[0] / (float)(NS * NS);
            g_red_count = 0;           // reset for graph replay
        }
    }
}

// ---------------------------------------------------------------------------
extern "C" void kernel_launch(void* const* d_in, const int* in_sizes, int n_in,
                              void* d_out, int out_size) {
    const float* features = (const float*)d_in[0];
    const int*   labels   = (const int*)d_in[1];
    (void)in_sizes; (void)n_in; (void)out_size;

    prep_kernel<<<1, NS>>>(labels);
    dim3 grid(MAXP, KSEG, KSPLIT);     // inactive pairs exit immediately
    gemm_kernel<<<grid, 128>>>(features);
    reduce_kernel<<<NCLASS * 64, 256>>>((float*)d_out);
}

// round 10
// speedup vs baseline: 3.6543x; 1.5776x over previous
#include <cuda_runtime.h>
#include <cuda_bf16.h>
#include <cstdint>

// ---------------- problem constants ----------------
#define NS      512
#define KSEG    16
#define SEGD    8192
#define FSTRIDE (KSEG * SEGD)
#define OP_SCALE 1.1952286093343936f   // 1/sqrt(0.7) folded per operand
#define NCLASS  10

// ---------------- GEMM config ----------------
#define MT      64                     // class tile
#define CK      64                     // bf16 cols per chunk (128B rows, SW128)
#define KSPLIT  4
#define KQ      (SEGD / KSPLIT)        // 2048
#define CHPU    (KQ / CK)              // 32 chunks per unit
#define STAGES  4
#define OP_BYTES    (MT * 128)         // 8192 per operand per stage
#define STAGE_BYTES (2 * OP_BYTES)     // 16384
#define SMEM_DYN (1024 + STAGES * STAGE_BYTES)  // 66560 -> 3 CTAs/SM

#define NROWPAD 640                    // grouped rows padded (zeros beyond 512)
#define MAXP    32                     // max class tile-pairs
#define NPL     (KSEG * KSPLIT)        // 64 gram planes

// ---------------- device scratch ----------------
__device__ __align__(16) __nv_bfloat16 g_fb16[(size_t)KSEG * NROWPAD * SEGD]; // [k][row][d]
__device__ float g_gram[(size_t)NPL * MAXP * MT * MT];  // 33.5 MB partials
__device__ float g_partials[1024];
__device__ int   g_red_count;
// schedule (rebuilt by prep every launch; deterministic)
__device__ int   g_pos[NS];            // original sample -> grouped row
__device__ int   g_cnum[NCLASS], g_cT[NCLASS], g_cpbase[NCLASS];
__device__ int   g_pairM[MAXP], g_pairN[MAXP];
__device__ int   g_P;

// ---------------- helpers ----------------
__device__ __forceinline__ uint32_t smem_u32(const void* p) {
    uint32_t a;
    asm("{ .reg .u64 t; cvta.to.shared.u64 t, %1; cvt.u32.u64 %0, t; }" : "=r"(a) : "l"(p));
    return a;
}
#define CP16(dst, src) \
    asm volatile("cp.async.cg.shared.global [%0], [%1], 16;" :: "r"(dst), "l"(src))
#define CP_COMMIT() asm volatile("cp.async.commit_group;" ::: "memory")
template <int N> __device__ __forceinline__ void cp_wait() {
    asm volatile("cp.async.wait_group %0;" :: "n"(N) : "memory");
}
#define SW128(o) ((o) ^ (((o) >> 3) & 0x70))

__device__ __forceinline__ void ldsm_x4(uint32_t& r0, uint32_t& r1, uint32_t& r2, uint32_t& r3,
                                        uint32_t addr) {
    asm volatile("ldmatrix.sync.aligned.m8n8.x4.shared.b16 {%0,%1,%2,%3}, [%4];"
                 : "=r"(r0), "=r"(r1), "=r"(r2), "=r"(r3) : "r"(addr));
}
__device__ __forceinline__ void mma16816(float* c, const uint32_t* a, uint32_t b0, uint32_t b1) {
    asm volatile(
        "mma.sync.aligned.m16n8k16.row.col.f32.bf16.bf16.f32 "
        "{%0,%1,%2,%3}, {%4,%5,%6,%7}, {%8,%9}, {%0,%1,%2,%3};"
        : "+f"(c[0]), "+f"(c[1]), "+f"(c[2]), "+f"(c[3])
        : "r"(a[0]), "r"(a[1]), "r"(a[2]), "r"(a[3]), "r"(b0), "r"(b1));
}

// ---------------------------------------------------------------------------
// Prep (1 block, 512 threads, ~2.5us): label dtype detect; stable grouping
// rank via __match_any_sync + per-warp class histograms; tile-pair schedule.
// Fully deterministic (no order-dependent atomics).
// ---------------------------------------------------------------------------
__global__ void prep_kernel(const int* __restrict__ lab) {
    __shared__ int wcnt[16][NCLASS];
    __shared__ int cnt[NCLASS], cstart[NCLASS];
    const int t = threadIdx.x;
    const int lane = t & 31, w = t >> 5;

    // int32 vs int64: labels 0..9 -> odd 32-bit words all zero iff int64
    int viol = (lab[2 * t + 1] != 0) ? 1 : 0;
    int is32 = __syncthreads_or(viol);
    const int v = is32 ? lab[t] : lab[2 * t];

    if (t < 16 * NCLASS) ((int*)wcnt)[t] = 0;
    __syncthreads();

    const unsigned m = __match_any_sync(0xffffffffu, v);
    const int riw = __popc(m & ((1u << lane) - 1));       // rank within warp
    if (lane == (__ffs(m) - 1)) wcnt[w][v] = __popc(m);   // leader stores count
    __syncthreads();

    int rank = riw;
    for (int ww = 0; ww < w; ww++) rank += wcnt[ww][v];

    if (t < NCLASS) {
        int s = 0;
        for (int ww = 0; ww < 16; ww++) s += wcnt[ww][t];
        cnt[t] = s;
    }
    __syncthreads();

    if (t == 0) {
        int start = 0, P = 0;
        for (int c = 0; c < NCLASS; c++) {
            const int n = cnt[c];
            cstart[c] = start;
            g_cnum[c] = n;
            const int T = (n + MT - 1) / MT;
            g_cT[c] = T;
            g_cpbase[c] = P;
            for (int ti = 0; ti < T; ti++)
                for (int tj = ti; tj < T; tj++) {
                    if (P < MAXP) { g_pairM[P] = start + MT * ti; g_pairN[P] = start + MT * tj; }
                    P++;
                }
            start += n;
        }
        g_P = (P > MAXP) ? MAXP : P;
    }
    __syncthreads();
    g_pos[t] = cstart[v] + rank;
}

// ---------------------------------------------------------------------------
// f32 -> bf16 with scale fold; layout [n][k][d] -> [k][grouped_row][d].
// Measured-at-floor traffic pattern (83.5% DRAM in R4).
// ---------------------------------------------------------------------------
__global__ __launch_bounds__(256) void convert_kernel(const float* __restrict__ F) {
    size_t t = (size_t)blockIdx.x * 256 + threadIdx.x;
    size_t e = t * 8;
    const float4* src = (const float4*)(F + e);
    float4 a = src[0], b = src[1];
    a.x *= OP_SCALE; a.y *= OP_SCALE; a.z *= OP_SCALE; a.w *= OP_SCALE;
    b.x *= OP_SCALE; b.y *= OP_SCALE; b.z *= OP_SCALE; b.w *= OP_SCALE;

    __nv_bfloat162 h0 = __floats2bfloat162_rn(a.x, a.y);
    __nv_bfloat162 h1 = __floats2bfloat162_rn(a.z, a.w);
    __nv_bfloat162 h2 = __floats2bfloat162_rn(b.x, b.y);
    __nv_bfloat162 h3 = __floats2bfloat162_rn(b.z, b.w);

    uint32_t r = (uint32_t)(e >> 13);       // n*16 + k
    uint32_t d = (uint32_t)(e & 8191);
    uint32_t n = r >> 4, k = r & 15;
    __nv_bfloat16* dst = g_fb16 + ((size_t)k * NROWPAD + g_pos[n]) * SEGD + d;
    uint4 w;
    w.x = *(uint32_t*)&h0; w.y = *(uint32_t*)&h1;
    w.z = *(uint32_t*)&h2; w.w = *(uint32_t*)&h3;
    *(uint4*)dst = w;
}

// ---------------------------------------------------------------------------
// Block-diagonal bf16 Gram GEMM, cp.async 4-stage (R4-proven pipeline).
// Grid (MAXP, KSEG, KSPLIT); pidx >= g_P exits. 128 threads, 2x2 warp grid
// of 32x32 tiles over a 64x64 class tile. Diagonal pairs load A only (B==A).
// ---------------------------------------------------------------------------
__global__ void __launch_bounds__(128)
gemm_kernel() {
    const int pidx = blockIdx.x;
    if (pidx >= g_P) return;
    const int seg = blockIdx.y;
    const int kq  = blockIdx.z;

    extern __shared__ __align__(1024) char smem_raw[];
    const uint32_t sbase = (smem_u32(smem_raw) + 1023) & ~1023u;

    const int tid  = threadIdx.x;
    const int lane = tid & 31;
    const int wid  = tid >> 5;
    const int wm   = wid & 1;
    const int wn   = wid >> 1;
    const int lrow = lane & 15;
    const int khf  = (lane >> 4) & 1;
    const int gid  = lane >> 2, tig = lane & 3;

    const int Moff = g_pairM[pidx];
    const int Noff = g_pairN[pidx];
    const bool diag = (Moff == Noff);

    const __nv_bfloat16* gA = g_fb16 + ((size_t)seg * NROWPAD + Moff) * SEGD + kq * KQ;
    const __nv_bfloat16* gB = g_fb16 + ((size_t)seg * NROWPAD + Noff) * SEGD + kq * KQ;

    float acc[2][4][4];
#pragma unroll
    for (int i = 0; i < 2; i++)
#pragma unroll
        for (int j = 0; j < 4; j++)
#pragma unroll
            for (int q = 0; q < 4; q++) acc[i][j][q] = 0.0f;

    auto load_chunk = [&](int c) {
        uint32_t st = sbase + (c & (STAGES - 1)) * STAGE_BYTES;
        int kb = c * CK;
#pragma unroll
        for (int i = 0; i < 4; i++) {            // A: 512 x 16B over 128 thr
            int q = i * 128 + tid;
            int row = q >> 3, g = q & 7;
            CP16(st + SW128(row * 128 + g * 16),
                 gA + (size_t)row * SEGD + kb + g * 8);
        }
        if (!diag) {
#pragma unroll
            for (int i = 0; i < 4; i++) {        // B: 512 x 16B
                int q = i * 128 + tid;
                int row = q >> 3, g = q & 7;
                CP16(st + OP_BYTES + SW128(row * 128 + g * 16),
                     gB + (size_t)row * SEGD + kb + g * 8);
            }
        }
        CP_COMMIT();
    };

    auto compute = [&](int cs) {
        const uint32_t sa = sbase + cs * STAGE_BYTES;
        const uint32_t sb = diag ? sa : (sa + OP_BYTES);
#pragma unroll
        for (int ks = 0; ks < 4; ks++) {
            const int kb = ks * 32 + khf * 16;
            uint32_t a[2][4], bf[2][4];
#pragma unroll
            for (int im = 0; im < 2; im++) {
                int row = wm * 32 + im * 16 + lrow;
                ldsm_x4(a[im][0], a[im][1], a[im][2], a[im][3],
                        sa + SW128(row * 128 + kb));
            }
#pragma unroll
            for (int j2 = 0; j2 < 2; j2++) {
                int row = wn * 32 + j2 * 16 + lrow;
                ldsm_x4(bf[j2][0], bf[j2][1], bf[j2][2], bf[j2][3],
                        sb + SW128(row * 128 + kb));
            }
#pragma unroll
            for (int im = 0; im < 2; im++)
#pragma unroll
                for (int jn = 0; jn < 4; jn++)
                    mma16816(acc[im][jn], a[im],
                             bf[jn >> 1][jn & 1], bf[jn >> 1][2 + (jn & 1)]);
        }
    };

    load_chunk(0); load_chunk(1); load_chunk(2);
    for (int c = 0; c < CHPU; c++) {
        cp_wait<2>();
        __syncthreads();
        compute(c & (STAGES - 1));
        if (c + 3 < CHPU) load_chunk(c + 3);
        else CP_COMMIT();                 // keep wait<2> group semantics
    }

    float* Cb = g_gram + ((size_t)(seg * KSPLIT + kq) * MAXP + pidx) * (MT * MT);
#pragma unroll
    for (int im = 0; im < 2; im++) {
#pragma unroll
        for (int jn = 0; jn < 4; jn++) {
            int r0 = wm * 32 + im * 16 + gid;
            int c0 = wn * 32 + jn * 8 + tig * 2;
            *(float2*)&Cb[r0 * MT + c0] =
                make_float2(acc[im][jn][0], acc[im][jn][1]);
            *(float2*)&Cb[(r0 + 8) * MT + c0] =
                make_float2(acc[im][jn][2], acc[im][jn][3]);
        }
    }
}

// ---------------------------------------------------------------------------
// Loss over within-class pairs only (i < j, weight 2). Sums 4 K-partials,
// top-4-of-16 exp ratio; deterministic tree reduce; last block writes mean.
// Grid: NCLASS x 64 blocks (i, j in [0,128) per class).
// ---------------------------------------------------------------------------
__global__ __launch_bounds__(256) void reduce_kernel(float* __restrict__ out) {
    const int t     = threadIdx.x;
    const int c     = blockIdx.x >> 6;
    const int local = ((blockIdx.x & 63) << 8) + t;
    const int i = local >> 7;
    const int j = local & 127;

    float loss = 0.0f;
    const int nc = g_cnum[c];
    if (i < j && j < nc) {
        const int T  = g_cT[c];
        const int ti = i >> 6, tj = j >> 6;
        const int pidx = g_cpbase[c] + ti * T - (ti * (ti - 1)) / 2 + (tj - ti);
        const int cell = (i & 63) * MT + (j & 63);

        float v[KSEG];
        float m = -1e30f;
#pragma unroll
        for (int k = 0; k < KSEG; k++) {
            float s = 0.0f;
#pragma unroll
            for (int kq = 0; kq < KSPLIT; kq++)
                s += g_gram[((size_t)(k * KSPLIT + kq) * MAXP + pidx) * (MT * MT) + cell];
            v[k] = s;
            m = fmaxf(m, s);
        }
        float tot = 0.0f, t0 = 0.0f, t1 = 0.0f, t2 = 0.0f, t3 = 0.0f;
#pragma unroll
        for (int k = 0; k < KSEG; k++) {
            const float e = __expf(v[k] - m);
            tot += e;
            if (e > t0)      { t3 = t2; t2 = t1; t1 = t0; t0 = e; }
            else if (e > t1) { t3 = t2; t2 = t1; t1 = e; }
            else if (e > t2) { t3 = t2; t2 = e; }
            else if (e > t3) { t3 = e; }
        }
        loss = -2.0f * __logf((t0 + t1 + t2 + t3) / tot);   // both (a,b),(b,a)
    }

    __shared__ float red[256];
    red[t] = loss;
    __syncthreads();
#pragma unroll
    for (int s = 128; s > 0; s >>= 1) {
        if (t < s) red[t] += red[t + s];
        __syncthreads();
    }

    __shared__ int isLast;
    if (t == 0) {
        g_partials[blockIdx.x] = red[0];
        __threadfence();
        int cn = atomicAdd(&g_red_count, 1);
        isLast = (cn == gridDim.x - 1);
    }
    __syncthreads();

    if (isLast) {
        float s = __ldcg(&g_partials[t]) + __ldcg(&g_partials[t + 256]);
        if (t + 512 < 640) s += __ldcg(&g_partials[t + 512]);
        red[t] = s;
        __syncthreads();
#pragma unroll
        for (int sh = 128; sh > 0; sh >>= 1) {
            if (t < sh) red[t] += red[t + sh];
            __syncthreads();
        }
        if (t == 0) {
            out[0] = red[0] / (float)(NS * NS);
            g_red_count = 0;           // reset for graph replay
        }
    }
}

// ---------------------------------------------------------------------------
extern "C" void kernel_launch(void* const* d_in, const int* in_sizes, int n_in,
                              void* d_out, int out_size) {
    const float* features = (const float*)d_in[0];
    const int*   labels   = (const int*)d_in[1];
    (void)in_sizes; (void)n_in; (void)out_size;

    cudaFuncSetAttribute(gemm_kernel, cudaFuncAttributeMaxDynamicSharedMemorySize, SMEM_DYN);

    prep_kernel<<<1, NS>>>(labels);
    convert_kernel<<<(NS * FSTRIDE) / (256 * 8), 256>>>(features);
    dim3 grid(MAXP, KSEG, KSPLIT);     // inactive pairs exit immediately
    gemm_kernel<<<grid, 128, SMEM_DYN>>>();
    reduce_kernel<<<NCLASS * 64, 256>>>((float*)d_out);
}